// round 6
// baseline (speedup 1.0000x reference)
#include <cuda_runtime.h>
#include <math.h>

#define B   2
#define NT  2048
#define DM  1024
#define H   16
#define HD  64
#define EPSF 1e-10f

__device__ float g_Q[(size_t)B*H*NT*HD];
__device__ float g_K[(size_t)B*H*NT*HD];
__device__ float g_V[(size_t)B*H*NT*HD];
__device__ float g_E[(size_t)B*H*NT*NT];     // exp(scores), unnormalized
__device__ float g_P[(size_t)B*NT*NT];
__device__ float g_ctx[(size_t)B*NT*DM];
__device__ float g_Z[(size_t)B*H*NT];
__device__ float g_T[(size_t)B*H*NT];
__device__ float g_Zi[(size_t)B*H*NT];
__device__ float g_colsum[B*NT];
__device__ float g_colpart[16*B*NT];

__device__ __forceinline__ unsigned cvt_tf32(float x){
    unsigned r; asm("cvt.rna.tf32.f32 %0, %1;" : "=r"(r) : "f"(x)); return r;
}
__device__ __forceinline__ void mma_tf32(float4 &c,
    unsigned a0, unsigned a1, unsigned a2, unsigned a3,
    unsigned b0, unsigned b1)
{
    asm("mma.sync.aligned.m16n8k8.row.col.f32.tf32.tf32.f32 "
        "{%0,%1,%2,%3},{%4,%5,%6,%7},{%8,%9},{%0,%1,%2,%3};"
        : "+f"(c.x), "+f"(c.y), "+f"(c.z), "+f"(c.w)
        : "r"(a0), "r"(a1), "r"(a2), "r"(a3), "r"(b0), "r"(b1));
}

// ---------------------------------------------------------------------------
// C[m][e] = sum_k A[m][k]*W[e][k] + bias[e].  128x128 tile, BK=16, tf32 mma.
// Software-pipelined: next chunk's LDG issued before current chunk's MMA.
// ---------------------------------------------------------------------------
__global__ __launch_bounds__(256, 2)
void gemm_nt_mma(const float* __restrict__ A, const float* __restrict__ W,
                 const float* __restrict__ bias, float* __restrict__ C,
                 int N, int K, int head_layout)
{
    __shared__ unsigned As[16][136];
    __shared__ unsigned Bs[16][136];
    const int tid = threadIdx.x, lane = tid & 31, warp = tid >> 5;
    const int gid = lane >> 2, tig = lane & 3;
    const int wm = warp & 1, wn = warp >> 1;
    const int bm0 = blockIdx.y * 128, bn0 = blockIdx.x * 128;
    const int lr = tid >> 1, lk = (tid & 1) * 8;
    const float* Ag = A + (size_t)(bm0 + lr) * K + lk;
    const float* Wg = W + (size_t)(bn0 + lr) * K + lk;

    float4 acc[4][4];
    #pragma unroll
    for (int i = 0; i < 4; i++)
        #pragma unroll
        for (int j = 0; j < 4; j++) acc[i][j] = make_float4(0.f,0.f,0.f,0.f);

    float4 pa0 = *(const float4*)(Ag);
    float4 pa1 = *(const float4*)(Ag + 4);
    float4 pw0 = *(const float4*)(Wg);
    float4 pw1 = *(const float4*)(Wg + 4);

    for (int k0 = 0; k0 < K; k0 += 16) {
        __syncthreads();
        As[lk+0][lr]=cvt_tf32(pa0.x); As[lk+1][lr]=cvt_tf32(pa0.y);
        As[lk+2][lr]=cvt_tf32(pa0.z); As[lk+3][lr]=cvt_tf32(pa0.w);
        As[lk+4][lr]=cvt_tf32(pa1.x); As[lk+5][lr]=cvt_tf32(pa1.y);
        As[lk+6][lr]=cvt_tf32(pa1.z); As[lk+7][lr]=cvt_tf32(pa1.w);
        Bs[lk+0][lr]=cvt_tf32(pw0.x); Bs[lk+1][lr]=cvt_tf32(pw0.y);
        Bs[lk+2][lr]=cvt_tf32(pw0.z); Bs[lk+3][lr]=cvt_tf32(pw0.w);
        Bs[lk+4][lr]=cvt_tf32(pw1.x); Bs[lk+5][lr]=cvt_tf32(pw1.y);
        Bs[lk+6][lr]=cvt_tf32(pw1.z); Bs[lk+7][lr]=cvt_tf32(pw1.w);
        __syncthreads();
        if (k0 + 16 < K) {
            pa0 = *(const float4*)(Ag + k0 + 16);
            pa1 = *(const float4*)(Ag + k0 + 20);
            pw0 = *(const float4*)(Wg + k0 + 16);
            pw1 = *(const float4*)(Wg + k0 + 20);
        }
        #pragma unroll
        for (int ks = 0; ks < 2; ks++) {
            const int kb = ks * 8;
            unsigned af[4][4];
            #pragma unroll
            for (int mt = 0; mt < 4; mt++) {
                int m = wm*64 + mt*16 + gid;
                af[mt][0] = As[kb+tig][m];     af[mt][1] = As[kb+tig][m+8];
                af[mt][2] = As[kb+tig+4][m];   af[mt][3] = As[kb+tig+4][m+8];
            }
            #pragma unroll
            for (int nt = 0; nt < 4; nt++) {
                int n = wn*32 + nt*8 + gid;
                unsigned b0 = Bs[kb+tig][n], b1 = Bs[kb+tig+4][n];
                #pragma unroll
                for (int mt = 0; mt < 4; mt++)
                    mma_tf32(acc[mt][nt], af[mt][0],af[mt][1],af[mt][2],af[mt][3], b0, b1);
            }
        }
    }

    #pragma unroll
    for (int mt = 0; mt < 4; mt++) {
        int r0 = bm0 + wm*64 + mt*16 + gid;
        #pragma unroll
        for (int nt = 0; nt < 4; nt++) {
            int c0 = bn0 + wn*32 + nt*8 + tig*2;
            float bx = bias[c0], by = bias[c0+1];
            float2 lo = make_float2(acc[mt][nt].x + bx, acc[mt][nt].y + by);
            float2 hi = make_float2(acc[mt][nt].z + bx, acc[mt][nt].w + by);
            if (head_layout) {
                int bb = r0 >> 11, tok = r0 & 2047, hh = c0 >> 6, hd = c0 & 63;
                float* p = C + (((size_t)(bb*H + hh)*NT + tok)*HD) + hd;
                *(float2*)p = lo;
                *(float2*)(p + 8*HD) = hi;
            } else {
                float* p = C + (size_t)r0*N + c0;
                *(float2*)p = lo;
                *(float2*)(p + 8*(size_t)N) = hi;
            }
        }
    }
}

// ---------------------------------------------------------------------------
// Fused scores + exp + row Z/T/Zi.  K-chunk stream linearized across j-tiles
// and software-pipelined (prefetch chunk c+1 during MMA of chunk c).
// ---------------------------------------------------------------------------
__global__ __launch_bounds__(256, 2)
void scores_exp_mma(const float* __restrict__ pbs, const int* __restrict__ perm)
{
    __shared__ unsigned Qs[64][136];
    __shared__ unsigned Ks[16][136];
    __shared__ float pfi[128], pfj[128];

    const int tid = threadIdx.x, lane = tid & 31, warp = tid >> 5;
    const int gid = lane >> 2, tig = lane & 3;
    const int wm = warp & 1, wn = warp >> 1;
    const int bh = blockIdx.y, b = bh >> 4, h = bh & 15;
    const int bi0 = blockIdx.x * 128;
    const float pb = fabsf(pbs[h]);

    const float* Qg = g_Q + ((size_t)bh*NT + bi0)*HD;
    const float* Kbase = g_K + (size_t)bh*NT*HD;
    const int lr = tid >> 1, lk = (tid & 1) * 8;
    #pragma unroll
    for (int c = 0; c < 4; c++) {
        int kk = lk + c*16;
        float4 q0 = *(const float4*)(Qg + (size_t)lr*HD + kk);
        float4 q1 = *(const float4*)(Qg + (size_t)lr*HD + kk + 4);
        Qs[kk+0][lr]=cvt_tf32(q0.x); Qs[kk+1][lr]=cvt_tf32(q0.y);
        Qs[kk+2][lr]=cvt_tf32(q0.z); Qs[kk+3][lr]=cvt_tf32(q0.w);
        Qs[kk+4][lr]=cvt_tf32(q1.x); Qs[kk+5][lr]=cvt_tf32(q1.y);
        Qs[kk+6][lr]=cvt_tf32(q1.z); Qs[kk+7][lr]=cvt_tf32(q1.w);
    }
    if (tid < 128) pfi[tid] = (float)perm[b*NT + bi0 + tid];

    float Zr[8] = {0,0,0,0,0,0,0,0};
    float Tr[8] = {0,0,0,0,0,0,0,0};

    // chunk c (0..63): j0 = (c>>2)*128, kc = (c&3)*16
    float4 pk0 = *(const float4*)(Kbase + (size_t)lr*HD + lk);
    float4 pk1 = *(const float4*)(Kbase + (size_t)lr*HD + lk + 4);

    for (int j0 = 0; j0 < NT; j0 += 128) {
        float4 acc[4][4];
        #pragma unroll
        for (int i = 0; i < 4; i++)
            #pragma unroll
            for (int j = 0; j < 4; j++) acc[i][j] = make_float4(0.f,0.f,0.f,0.f);

        #pragma unroll
        for (int kc = 0; kc < 64; kc += 16) {
            __syncthreads();
            Ks[lk+0][lr]=cvt_tf32(pk0.x); Ks[lk+1][lr]=cvt_tf32(pk0.y);
            Ks[lk+2][lr]=cvt_tf32(pk0.z); Ks[lk+3][lr]=cvt_tf32(pk0.w);
            Ks[lk+4][lr]=cvt_tf32(pk1.x); Ks[lk+5][lr]=cvt_tf32(pk1.y);
            Ks[lk+6][lr]=cvt_tf32(pk1.z); Ks[lk+7][lr]=cvt_tf32(pk1.w);
            if (kc == 0 && tid < 128) pfj[tid] = (float)perm[b*NT + j0 + tid];
            __syncthreads();
            // prefetch next chunk (crossing into next j-tile when kc==48)
            {
                int nj0 = (kc < 48) ? j0 : j0 + 128;
                int nkc = (kc < 48) ? kc + 16 : 0;
                if (nj0 < NT) {
                    const float* Kg = Kbase + (size_t)(nj0 + lr)*HD + nkc + lk;
                    pk0 = *(const float4*)(Kg);
                    pk1 = *(const float4*)(Kg + 4);
                }
            }
            #pragma unroll
            for (int ks = 0; ks < 2; ks++) {
                const int kb = ks * 8;
                unsigned af[4][4];
                #pragma unroll
                for (int mt = 0; mt < 4; mt++) {
                    int m = wm*64 + mt*16 + gid;
                    af[mt][0] = Qs[kc+kb+tig][m];     af[mt][1] = Qs[kc+kb+tig][m+8];
                    af[mt][2] = Qs[kc+kb+tig+4][m];   af[mt][3] = Qs[kc+kb+tig+4][m+8];
                }
                #pragma unroll
                for (int nt = 0; nt < 4; nt++) {
                    int n = wn*32 + nt*8 + gid;
                    unsigned b0 = Ks[kb+tig][n], b1 = Ks[kb+tig+4][n];
                    #pragma unroll
                    for (int mt = 0; mt < 4; mt++)
                        mma_tf32(acc[mt][nt], af[mt][0],af[mt][1],af[mt][2],af[mt][3], b0, b1);
                }
            }
        }

        #pragma unroll
        for (int mt = 0; mt < 4; mt++) {
            int rl = wm*64 + mt*16 + gid;
            float pa = pfi[rl], pc = pfi[rl+8];
            #pragma unroll
            for (int nt = 0; nt < 4; nt++) {
                int cl = wn*32 + nt*8 + tig*2;
                float d0 = pfj[cl], d1 = pfj[cl+1];
                float4 a = acc[mt][nt];
                float s00 = a.x*0.125f - fabsf(pa - d0)*pb;
                float s01 = a.y*0.125f - fabsf(pa - d1)*pb;
                float s10 = a.z*0.125f - fabsf(pc - d0)*pb;
                float s11 = a.w*0.125f - fabsf(pc - d1)*pb;
                float e00 = __expf(s00), e01 = __expf(s01);
                float e10 = __expf(s10), e11 = __expf(s11);
                Zr[mt*2]   += e00 + e01;  Tr[mt*2]   += s00*e00 + s01*e01;
                Zr[mt*2+1] += e10 + e11;  Tr[mt*2+1] += s10*e10 + s11*e11;
                size_t base = ((size_t)bh*NT + bi0 + rl)*NT + j0 + cl;
                *(float2*)(g_E + base)        = make_float2(e00, e01);
                *(float2*)(g_E + base + 8*NT) = make_float2(e10, e11);
            }
        }
    }

    float* red = (float*)&Qs[0][0];
    const int pcol = wn*4 + tig;
    __syncthreads();
    #pragma unroll
    for (int mt = 0; mt < 4; mt++) {
        int r0 = wm*64 + mt*16 + gid;
        red[pcol*128 + r0]     = Zr[mt*2];
        red[pcol*128 + r0 + 8] = Zr[mt*2+1];
    }
    __syncthreads();
    if (tid < 128) {
        float s = 0.f;
        #pragma unroll
        for (int t = 0; t < 16; t++) s += red[t*128 + tid];
        g_Z[(size_t)bh*NT + bi0 + tid]  = s;
        g_Zi[(size_t)bh*NT + bi0 + tid] = 1.0f / s;
    }
    __syncthreads();
    #pragma unroll
    for (int mt = 0; mt < 4; mt++) {
        int r0 = wm*64 + mt*16 + gid;
        red[pcol*128 + r0]     = Tr[mt*2];
        red[pcol*128 + r0 + 8] = Tr[mt*2+1];
    }
    __syncthreads();
    if (tid < 128) {
        float s = 0.f;
        #pragma unroll
        for (int t = 0; t < 16; t++) s += red[t*128 + tid];
        g_T[(size_t)bh*NT + bi0 + tid] = s;
    }
}

// ---------------------------------------------------------------------------
// ctx = (E @ V) / Z, software-pipelined.  Block 128x64.
// ---------------------------------------------------------------------------
__global__ __launch_bounds__(256, 2)
void av_mma()
{
    __shared__ unsigned As[16][136];
    __shared__ unsigned Vs[16][72];
    __shared__ float zin[128];

    const int tid = threadIdx.x, lane = tid & 31, warp = tid >> 5;
    const int gid = lane >> 2, tig = lane & 3;
    const int wm = warp >> 1, wn = warp & 1;
    const int bh = blockIdx.y, b = bh >> 4, h = bh & 15;
    const int bi0 = blockIdx.x * 128;

    const int lr = tid >> 1, lk = (tid & 1) * 8;
    const float* Eg = g_E + ((size_t)bh*NT + bi0 + lr)*NT + lk;
    const float* Vg = g_V + (size_t)bh*NT*HD;
    const int vk = tid >> 4, vc = (tid & 15) * 4;

    if (tid < 128) zin[tid] = g_Zi[(size_t)bh*NT + bi0 + tid];

    float4 acc[2][4];
    #pragma unroll
    for (int i = 0; i < 2; i++)
        #pragma unroll
        for (int j = 0; j < 4; j++) acc[i][j] = make_float4(0.f,0.f,0.f,0.f);

    float4 pa0 = *(const float4*)(Eg);
    float4 pa1 = *(const float4*)(Eg + 4);
    float4 pvv = *(const float4*)(Vg + (size_t)vk*HD + vc);

    for (int k0 = 0; k0 < NT; k0 += 16) {
        __syncthreads();
        As[lk+0][lr]=cvt_tf32(pa0.x); As[lk+1][lr]=cvt_tf32(pa0.y);
        As[lk+2][lr]=cvt_tf32(pa0.z); As[lk+3][lr]=cvt_tf32(pa0.w);
        As[lk+4][lr]=cvt_tf32(pa1.x); As[lk+5][lr]=cvt_tf32(pa1.y);
        As[lk+6][lr]=cvt_tf32(pa1.z); As[lk+7][lr]=cvt_tf32(pa1.w);
        Vs[vk][vc+0]=cvt_tf32(pvv.x); Vs[vk][vc+1]=cvt_tf32(pvv.y);
        Vs[vk][vc+2]=cvt_tf32(pvv.z); Vs[vk][vc+3]=cvt_tf32(pvv.w);
        __syncthreads();
        if (k0 + 16 < NT) {
            pa0 = *(const float4*)(Eg + k0 + 16);
            pa1 = *(const float4*)(Eg + k0 + 20);
            pvv = *(const float4*)(Vg + (size_t)(k0 + 16 + vk)*HD + vc);
        }
        #pragma unroll
        for (int ks = 0; ks < 2; ks++) {
            const int kb = ks * 8;
            unsigned af[2][4];
            #pragma unroll
            for (int mt = 0; mt < 2; mt++) {
                int m = wm*32 + mt*16 + gid;
                af[mt][0] = As[kb+tig][m];     af[mt][1] = As[kb+tig][m+8];
                af[mt][2] = As[kb+tig+4][m];   af[mt][3] = As[kb+tig+4][m+8];
            }
            #pragma unroll
            for (int nt = 0; nt < 4; nt++) {
                int n = wn*32 + nt*8 + gid;
                unsigned b0 = Vs[kb+tig][n], b1 = Vs[kb+tig+4][n];
                #pragma unroll
                for (int mt = 0; mt < 2; mt++)
                    mma_tf32(acc[mt][nt], af[mt][0],af[mt][1],af[mt][2],af[mt][3], b0, b1);
            }
        }
    }

    #pragma unroll
    for (int mt = 0; mt < 2; mt++) {
        int rl = wm*32 + mt*16 + gid;
        float z0 = zin[rl], z1 = zin[rl+8];
        #pragma unroll
        for (int nt = 0; nt < 4; nt++) {
            int cl = wn*32 + nt*8 + tig*2;
            float4 a = acc[mt][nt];
            size_t base = ((size_t)b*NT + bi0 + rl)*DM + h*HD + cl;
            *(float2*)(g_ctx + base)        = make_float2(a.x*z0, a.y*z0);
            *(float2*)(g_ctx + base + 8*DM) = make_float2(a.z*z1, a.w*z1);
        }
    }
}

// ---------------------------------------------------------------------------
__global__ __launch_bounds__(256)
void build_P_rownorm()
{
    const int rowi = blockIdx.x;
    const int b = rowi >> 11, i = rowi & 2047;
    const int tid = threadIdx.x;
    __shared__ float red[256];

    float v[8] = {0,0,0,0,0,0,0,0};
    #pragma unroll
    for (int h = 0; h < H; h++) {
        const float* ep = g_E + ((size_t)(b*H + h)*NT + i)*NT;
        float zi = g_Zi[(size_t)(b*H + h)*NT + i];
        #pragma unroll
        for (int k = 0; k < 8; k++)
            v[k] += ep[tid + k*256] * zi;
    }
    float s = 0.f;
    #pragma unroll
    for (int k = 0; k < 8; k++) {
        v[k] = expf(logf(v[k] * (1.0f/16.0f) + EPSF) * 10.0f);
        s += v[k];
    }
    red[tid] = s; __syncthreads();
    for (int o = 128; o > 0; o >>= 1) { if (tid < o) red[tid] += red[tid+o]; __syncthreads(); }
    float inv = 1.0f / (red[0] + EPSF);
    float* rp = g_P + (size_t)rowi * NT;
    #pragma unroll
    for (int k = 0; k < 8; k++) rp[tid + k*256] = v[k] * inv;
}

__global__ __launch_bounds__(256)
void colsum_part()
{
    const int j  = blockIdx.x * 256 + threadIdx.x;
    const int ch = blockIdx.y;
    const int b  = blockIdx.z;
    const float* p = g_P + (size_t)b*NT*NT + (size_t)ch*128*NT + j;
    float s = 0.f;
    #pragma unroll 8
    for (int i = 0; i < 128; i++) s += p[(size_t)i*NT];
    g_colpart[(ch*B + b)*NT + j] = s;
}

__global__ __launch_bounds__(256)
void colsum_combine()
{
    const int idx = blockIdx.x * 256 + threadIdx.x;
    const int b = idx >> 11, j = idx & 2047;
    float s = 0.f;
    #pragma unroll
    for (int ch = 0; ch < 16; ch++) s += g_colpart[(ch*B + b)*NT + j];
    g_colsum[idx] = s;
}

__global__ __launch_bounds__(256)
void coldiv_rownorm_kernel()
{
    const size_t rowi = blockIdx.x;
    const int b = (int)(rowi >> 11);
    float* rp = g_P + rowi * NT;
    const int tid = threadIdx.x;
    __shared__ float red[256];
    float v[8]; float s = 0.f;
    #pragma unroll
    for (int k = 0; k < 8; k++) {
        int j = tid + k*256;
        v[k] = rp[j] / (g_colsum[b*NT + j] + EPSF);
        s += v[k];
    }
    red[tid] = s; __syncthreads();
    for (int o = 128; o > 0; o >>= 1) { if (tid < o) red[tid] += red[tid+o]; __syncthreads(); }
    float inv = 1.0f / (red[0] + EPSF);
    #pragma unroll
    for (int k = 0; k < 8; k++) rp[tid + k*256] = v[k] * inv;
}

__global__ __launch_bounds__(256)
void cert_kernel(const float* __restrict__ cert, const float* __restrict__ ctemp,
                 float* __restrict__ out)
{
    const int idx = blockIdx.x * 256 + threadIdx.x;
    const int b = idx >> 11, i = idx & 2047;
    float s = 0.f;
    #pragma unroll
    for (int h = 0; h < H; h++) {
        size_t o = (size_t)(b*H + h)*NT + i;
        float Z = g_Z[o];
        s += logf(Z) - g_T[o] / Z;
    }
    float ent = s * (1.0f / 16.0f);
    float z = ctemp[0] * (logf(2048.0f) - ent);
    out[idx] = fmaxf(cert[idx], 1.0f / (1.0f + expf(-z)));
}

__global__ __launch_bounds__(256)
void argmax_gather_kernel(const int* __restrict__ perm, float* __restrict__ out)
{
    const int rowi = blockIdx.x;
    const int b = rowi >> 11;
    const float* rp = g_P + (size_t)rowi * NT;
    const int tid = threadIdx.x;
    __shared__ float bv[256];
    __shared__ int   bi[256];

    float best = -INFINITY; int bj = NT;
    #pragma unroll
    for (int s = 0; s < 8; s++) {
        int j = tid + s*256;
        float v = rp[j] / (g_colsum[b*NT + j] + EPSF);
        if (v > best) { best = v; bj = j; }
    }
    bv[tid] = best; bi[tid] = bj; __syncthreads();
    for (int o = 128; o > 0; o >>= 1) {
        if (tid < o) {
            if (bv[tid+o] > bv[tid] || (bv[tid+o] == bv[tid] && bi[tid+o] < bi[tid])) {
                bv[tid] = bv[tid+o]; bi[tid] = bi[tid+o];
            }
        }
        __syncthreads();
    }
    if (tid == 0) out[rowi] = (float)perm[(size_t)b*NT + bi[0]];
}

extern "C" void kernel_launch(void* const* d_in, const int* in_sizes, int n_in,
                              void* d_out, int out_size)
{
    const float* x     = (const float*)d_in[0];
    const float* cert  = (const float*)d_in[1];
    const int*   perm  = (const int*)  d_in[2];
    const float* Wq    = (const float*)d_in[3];
    const float* bq    = (const float*)d_in[4];
    const float* Wk    = (const float*)d_in[5];
    const float* bk    = (const float*)d_in[6];
    const float* Wv    = (const float*)d_in[7];
    const float* bvv   = (const float*)d_in[8];
    const float* Wo    = (const float*)d_in[9];
    const float* bo    = (const float*)d_in[10];
    const float* pbs   = (const float*)d_in[11];
    const float* ctemp = (const float*)d_in[12];
    float* out = (float*)d_out;

    float *pQ, *pK, *pV, *pCtx;
    cudaGetSymbolAddress((void**)&pQ,   g_Q);
    cudaGetSymbolAddress((void**)&pK,   g_K);
    cudaGetSymbolAddress((void**)&pV,   g_V);
    cudaGetSymbolAddress((void**)&pCtx, g_ctx);

    const int M = B * NT;                  // 4096

    dim3 gProj(DM/128, M/128);             // (8, 32)
    gemm_nt_mma<<<gProj, 256>>>(x, Wq, bq, pQ, DM, DM, 1);
    gemm_nt_mma<<<gProj, 256>>>(x, Wk, bk, pK, DM, DM, 1);
    gemm_nt_mma<<<gProj, 256>>>(x, Wv, bvv, pV, DM, DM, 1);

    dim3 gS(NT/128, B*H);                  // (16, 32)
    scores_exp_mma<<<gS, 256>>>(pbs, perm);

    av_mma<<<gS, 256>>>();

    gemm_nt_mma<<<gProj, 256>>>(pCtx, Wo, bo, out, DM, DM, 0);

    cert_kernel<<<(B*NT)/256, 256>>>(cert, ctemp, out + (size_t)M*DM);

    build_P_rownorm<<<B*NT, 256>>>();
    for (int it = 0; it < 10; it++) {
        colsum_part<<<dim3(NT/256, 16, B), 256>>>();
        colsum_combine<<<(B*NT)/256, 256>>>();
        if (it < 9) coldiv_rownorm_kernel<<<B*NT, 256>>>();
    }
    argmax_gather_kernel<<<B*NT, 256>>>(perm, out + (size_t)M*DM + B*NT);
}

// round 7
// speedup vs baseline: 1.1965x; 1.1965x over previous
#include <cuda_runtime.h>
#include <math.h>

#define B   2
#define NT  2048
#define DM  1024
#define H   16
#define HD  64
#define EPSF 1e-10f

__device__ float g_Q[(size_t)B*H*NT*HD];
__device__ float g_K[(size_t)B*H*NT*HD];
__device__ float g_V[(size_t)B*H*NT*HD];
__device__ float g_E[(size_t)B*H*NT*NT];     // exp(scores), unnormalized
__device__ float g_P[(size_t)B*NT*NT];
__device__ float g_ctx[(size_t)B*NT*DM];
__device__ float g_Z[(size_t)B*H*NT];
__device__ float g_T[(size_t)B*H*NT];
__device__ float g_Zi[(size_t)B*H*NT];
__device__ float g_colsum[B*NT];
__device__ float g_colpart[16*B*NT];

__device__ __forceinline__ unsigned cvt_tf32(float x){
    unsigned r; asm("cvt.rna.tf32.f32 %0, %1;" : "=r"(r) : "f"(x)); return r;
}
__device__ __forceinline__ void mma_tf32(float4 &c,
    unsigned a0, unsigned a1, unsigned a2, unsigned a3,
    unsigned b0, unsigned b1)
{
    asm("mma.sync.aligned.m16n8k8.row.col.f32.tf32.tf32.f32 "
        "{%0,%1,%2,%3},{%4,%5,%6,%7},{%8,%9},{%0,%1,%2,%3};"
        : "+f"(c.x), "+f"(c.y), "+f"(c.z), "+f"(c.w)
        : "r"(a0), "r"(a1), "r"(a2), "r"(a3), "r"(b0), "r"(b1));
}
__device__ __forceinline__ void cp16(unsigned d, const void* s){
    asm volatile("cp.async.cg.shared.global [%0], [%1], 16;\n" :: "r"(d), "l"(s));
}
__device__ __forceinline__ void cp_commit(){ asm volatile("cp.async.commit_group;\n"); }
__device__ __forceinline__ void cp_wait1(){ asm volatile("cp.async.wait_group 1;\n" ::: "memory"); }
__device__ __forceinline__ void cp_wait0(){ asm volatile("cp.async.wait_group 0;\n" ::: "memory"); }

// ---------------------------------------------------------------------------
// C[m][e] = sum_k A[m][k]*W[e][k] + bias[e].  128x128 tile, BK=16, tf32 mma,
// 3-stage cp.async pipeline, raw-fp32 smem [row][k] with pad 20.
// dynamic smem: As 3*128*20 + Bs 3*128*20 floats = 61440 B
// ---------------------------------------------------------------------------
__global__ __launch_bounds__(256, 2)
void gemm_nt_mma(const float* __restrict__ A, const float* __restrict__ W,
                 const float* __restrict__ bias, float* __restrict__ C,
                 int N, int K, int head_layout)
{
    extern __shared__ float smg[];
    float* Asm = smg;                // [3][128][20]
    float* Bsm = smg + 3*128*20;
    const unsigned sA = (unsigned)__cvta_generic_to_shared(Asm);
    const unsigned sB = (unsigned)__cvta_generic_to_shared(Bsm);

    const int tid = threadIdx.x, lane = tid & 31, warp = tid >> 5;
    const int gid = lane >> 2, tig = lane & 3;
    const int wm = warp & 1, wn = warp >> 1;
    const int bm0 = blockIdx.y * 128, bn0 = blockIdx.x * 128;
    const int lr = tid >> 1, lkq = (tid & 1) * 8;
    const float* Ag = A + (size_t)(bm0 + lr) * K + lkq;
    const float* Wg = W + (size_t)(bn0 + lr) * K + lkq;
    const int NCH = K / 16;

    float4 acc[4][4];
    #pragma unroll
    for (int i = 0; i < 4; i++)
        #pragma unroll
        for (int j = 0; j < 4; j++) acc[i][j] = make_float4(0.f,0.f,0.f,0.f);

    auto issue = [&](int cc){
        int st = cc % 3, k0 = cc * 16;
        unsigned da = sA + (unsigned)(((st*128 + lr)*20 + lkq)*4);
        cp16(da,      Ag + k0);
        cp16(da + 16, Ag + k0 + 4);
        unsigned db = sB + (unsigned)(((st*128 + lr)*20 + lkq)*4);
        cp16(db,      Wg + k0);
        cp16(db + 16, Wg + k0 + 4);
        cp_commit();
    };

    issue(0); issue(1);

    for (int c = 0; c < NCH; c++) {
        if (c + 1 < NCH) cp_wait1(); else cp_wait0();
        __syncthreads();
        if (c + 2 < NCH) issue(c + 2);
        const float* As_ = Asm + (c % 3)*128*20;
        const float* Bs_ = Bsm + (c % 3)*128*20;
        #pragma unroll
        for (int ks = 0; ks < 2; ks++) {
            const int kb = ks * 8;
            unsigned af[4][4];
            #pragma unroll
            for (int mt = 0; mt < 4; mt++) {
                int m = wm*64 + mt*16 + gid;
                af[mt][0] = cvt_tf32(As_[m*20     + kb + tig]);
                af[mt][1] = cvt_tf32(As_[(m+8)*20 + kb + tig]);
                af[mt][2] = cvt_tf32(As_[m*20     + kb + tig + 4]);
                af[mt][3] = cvt_tf32(As_[(m+8)*20 + kb + tig + 4]);
            }
            #pragma unroll
            for (int nt = 0; nt < 4; nt++) {
                int n = wn*32 + nt*8 + gid;
                unsigned b0 = cvt_tf32(Bs_[n*20 + kb + tig]);
                unsigned b1 = cvt_tf32(Bs_[n*20 + kb + tig + 4]);
                #pragma unroll
                for (int mt = 0; mt < 4; mt++)
                    mma_tf32(acc[mt][nt], af[mt][0],af[mt][1],af[mt][2],af[mt][3], b0, b1);
            }
        }
    }

    #pragma unroll
    for (int mt = 0; mt < 4; mt++) {
        int r0 = bm0 + wm*64 + mt*16 + gid;
        #pragma unroll
        for (int nt = 0; nt < 4; nt++) {
            int c0 = bn0 + wn*32 + nt*8 + tig*2;
            float bx = bias[c0], by = bias[c0+1];
            float2 lo = make_float2(acc[mt][nt].x + bx, acc[mt][nt].y + by);
            float2 hi = make_float2(acc[mt][nt].z + bx, acc[mt][nt].w + by);
            if (head_layout) {
                int bb = r0 >> 11, tok = r0 & 2047, hh = c0 >> 6, hd = c0 & 63;
                float* p = C + (((size_t)(bb*H + hh)*NT + tok)*HD) + hd;
                *(float2*)p = lo;
                *(float2*)(p + 8*HD) = hi;
            } else {
                float* p = C + (size_t)r0*N + c0;
                *(float2*)p = lo;
                *(float2*)(p + 8*(size_t)N) = hi;
            }
        }
    }
}

// ---------------------------------------------------------------------------
// Fused scores + exp + row Z/T/Zi.  3-stage cp.async on K tiles, chunk stream
// linearized across j-tiles.  dynamic smem:
//   Qs [128][68] raw fp32 (8704 f) | Ks [3][128][20] (7680 f) | pfi,pfj (256 f)
//   total 16640 floats = 66560 B
// ---------------------------------------------------------------------------
__global__ __launch_bounds__(256, 2)
void scores_exp_mma(const float* __restrict__ pbs, const int* __restrict__ perm)
{
    extern __shared__ float sms[];
    float* Qs  = sms;                    // [128][68]
    float* Ksm = sms + 8704;             // [3][128][20]
    float* pfi = sms + 8704 + 7680;
    float* pfj = pfi + 128;
    const unsigned sK = (unsigned)__cvta_generic_to_shared(Ksm);

    const int tid = threadIdx.x, lane = tid & 31, warp = tid >> 5;
    const int gid = lane >> 2, tig = lane & 3;
    const int wm = warp & 1, wn = warp >> 1;
    const int bh = blockIdx.y, b = bh >> 4, h = bh & 15;
    const int bi0 = blockIdx.x * 128;
    const float pb = fabsf(pbs[h]);

    const float* Qg = g_Q + ((size_t)bh*NT + bi0)*HD;
    const float* Kbase = g_K + (size_t)bh*NT*HD;
    const int lr = tid >> 1, lkq = (tid & 1) * 8;

    // stage Q (raw fp32)
    #pragma unroll
    for (int cq = 0; cq < 4; cq++) {
        int kk = lkq + cq*16;
        float4 q0 = *(const float4*)(Qg + (size_t)lr*HD + kk);
        float4 q1 = *(const float4*)(Qg + (size_t)lr*HD + kk + 4);
        *(float4*)&Qs[lr*68 + kk]     = q0;
        *(float4*)&Qs[lr*68 + kk + 4] = q1;
    }
    if (tid < 128) pfi[tid] = (float)perm[b*NT + bi0 + tid];

    float Zr[8] = {0,0,0,0,0,0,0,0};
    float Tr[8] = {0,0,0,0,0,0,0,0};

    auto issue = [&](int cc){
        int st = cc % 3, jt = cc >> 2, kc = (cc & 3) * 16;
        unsigned d = sK + (unsigned)(((st*128 + lr)*20 + lkq)*4);
        const float* s = Kbase + (size_t)(jt*128 + lr)*HD + kc + lkq;
        cp16(d, s); cp16(d + 16, s + 4);
        cp_commit();
    };

    issue(0); issue(1);
    const int NCH = 64;

    for (int jt = 0; jt < 16; jt++) {
        const int j0 = jt * 128;
        float4 acc[4][4];
        #pragma unroll
        for (int i = 0; i < 4; i++)
            #pragma unroll
            for (int j = 0; j < 4; j++) acc[i][j] = make_float4(0.f,0.f,0.f,0.f);

        #pragma unroll
        for (int k4 = 0; k4 < 4; k4++) {
            const int c = jt*4 + k4;
            if (c + 1 < NCH) cp_wait1(); else cp_wait0();
            __syncthreads();
            if (c + 2 < NCH) issue(c + 2);
            if (k4 == 0 && tid < 128) pfj[tid] = (float)perm[b*NT + j0 + tid];
            const float* Ks_ = Ksm + (c % 3)*128*20;
            const int kc = k4 * 16;
            #pragma unroll
            for (int ks = 0; ks < 2; ks++) {
                const int kb = ks * 8;
                unsigned af[4][4];
                #pragma unroll
                for (int mt = 0; mt < 4; mt++) {
                    int m = wm*64 + mt*16 + gid;
                    af[mt][0] = cvt_tf32(Qs[m*68     + kc + kb + tig]);
                    af[mt][1] = cvt_tf32(Qs[(m+8)*68 + kc + kb + tig]);
                    af[mt][2] = cvt_tf32(Qs[m*68     + kc + kb + tig + 4]);
                    af[mt][3] = cvt_tf32(Qs[(m+8)*68 + kc + kb + tig + 4]);
                }
                #pragma unroll
                for (int nt = 0; nt < 4; nt++) {
                    int n = wn*32 + nt*8 + gid;
                    unsigned b0 = cvt_tf32(Ks_[n*20 + kb + tig]);
                    unsigned b1 = cvt_tf32(Ks_[n*20 + kb + tig + 4]);
                    #pragma unroll
                    for (int mt = 0; mt < 4; mt++)
                        mma_tf32(acc[mt][nt], af[mt][0],af[mt][1],af[mt][2],af[mt][3], b0, b1);
                }
            }
        }

        #pragma unroll
        for (int mt = 0; mt < 4; mt++) {
            int rl = wm*64 + mt*16 + gid;
            float pa = pfi[rl], pc = pfi[rl+8];
            #pragma unroll
            for (int nt = 0; nt < 4; nt++) {
                int cl = wn*32 + nt*8 + tig*2;
                float d0 = pfj[cl], d1 = pfj[cl+1];
                float4 a = acc[mt][nt];
                float s00 = a.x*0.125f - fabsf(pa - d0)*pb;
                float s01 = a.y*0.125f - fabsf(pa - d1)*pb;
                float s10 = a.z*0.125f - fabsf(pc - d0)*pb;
                float s11 = a.w*0.125f - fabsf(pc - d1)*pb;
                float e00 = __expf(s00), e01 = __expf(s01);
                float e10 = __expf(s10), e11 = __expf(s11);
                Zr[mt*2]   += e00 + e01;  Tr[mt*2]   += s00*e00 + s01*e01;
                Zr[mt*2+1] += e10 + e11;  Tr[mt*2+1] += s10*e10 + s11*e11;
                size_t base = ((size_t)bh*NT + bi0 + rl)*NT + j0 + cl;
                *(float2*)(g_E + base)        = make_float2(e00, e01);
                *(float2*)(g_E + base + 8*NT) = make_float2(e10, e11);
            }
        }
    }

    float* red = Qs;   // Q no longer needed
    const int pcol = wn*4 + tig;
    __syncthreads();
    #pragma unroll
    for (int mt = 0; mt < 4; mt++) {
        int r0 = wm*64 + mt*16 + gid;
        red[pcol*128 + r0]     = Zr[mt*2];
        red[pcol*128 + r0 + 8] = Zr[mt*2+1];
    }
    __syncthreads();
    if (tid < 128) {
        float s = 0.f;
        #pragma unroll
        for (int t = 0; t < 16; t++) s += red[t*128 + tid];
        g_Z[(size_t)bh*NT + bi0 + tid]  = s;
        g_Zi[(size_t)bh*NT + bi0 + tid] = 1.0f / s;
    }
    __syncthreads();
    #pragma unroll
    for (int mt = 0; mt < 4; mt++) {
        int r0 = wm*64 + mt*16 + gid;
        red[pcol*128 + r0]     = Tr[mt*2];
        red[pcol*128 + r0 + 8] = Tr[mt*2+1];
    }
    __syncthreads();
    if (tid < 128) {
        float s = 0.f;
        #pragma unroll
        for (int t = 0; t < 16; t++) s += red[t*128 + tid];
        g_T[(size_t)bh*NT + bi0 + tid] = s;
    }
}

// ---------------------------------------------------------------------------
// ctx = (E @ V) / Z.  3-stage cp.async; static smem (45 KB).
// ---------------------------------------------------------------------------
__global__ __launch_bounds__(256, 2)
void av_mma()
{
    __shared__ float Es[3][128][20];
    __shared__ float Vs[3][16][72];
    __shared__ float zin[128];
    const unsigned sE = (unsigned)__cvta_generic_to_shared(&Es[0][0][0]);
    const unsigned sV = (unsigned)__cvta_generic_to_shared(&Vs[0][0][0]);

    const int tid = threadIdx.x, lane = tid & 31, warp = tid >> 5;
    const int gid = lane >> 2, tig = lane & 3;
    const int wm = warp >> 1, wn = warp & 1;
    const int bh = blockIdx.y, b = bh >> 4, h = bh & 15;
    const int bi0 = blockIdx.x * 128;

    const int lr = tid >> 1, lkq = (tid & 1) * 8;
    const float* Eg = g_E + ((size_t)bh*NT + bi0 + lr)*NT + lkq;
    const float* Vg = g_V + (size_t)bh*NT*HD;
    const int vr = tid >> 4, vcq = (tid & 15) * 4;

    if (tid < 128) zin[tid] = g_Zi[(size_t)bh*NT + bi0 + tid];

    float4 acc[2][4];
    #pragma unroll
    for (int i = 0; i < 2; i++)
        #pragma unroll
        for (int j = 0; j < 4; j++) acc[i][j] = make_float4(0.f,0.f,0.f,0.f);

    auto issue = [&](int cc){
        int st = cc % 3, k0 = cc * 16;
        unsigned dE = sE + (unsigned)(((st*128 + lr)*20 + lkq)*4);
        cp16(dE,      Eg + k0);
        cp16(dE + 16, Eg + k0 + 4);
        unsigned dV = sV + (unsigned)(((st*16 + vr)*72 + vcq)*4);
        cp16(dV, Vg + (size_t)(k0 + vr)*HD + vcq);
        cp_commit();
    };

    issue(0); issue(1);
    const int NCH = NT / 16;   // 128

    for (int c = 0; c < NCH; c++) {
        if (c + 1 < NCH) cp_wait1(); else cp_wait0();
        __syncthreads();
        if (c + 2 < NCH) issue(c + 2);
        const float* Es_ = &Es[c % 3][0][0];
        const float* Vs_ = &Vs[c % 3][0][0];
        #pragma unroll
        for (int ks = 0; ks < 2; ks++) {
            const int kb = ks * 8;
            unsigned af[2][4];
            #pragma unroll
            for (int mt = 0; mt < 2; mt++) {
                int m = wm*32 + mt*16 + gid;
                af[mt][0] = cvt_tf32(Es_[m*20     + kb + tig]);
                af[mt][1] = cvt_tf32(Es_[(m+8)*20 + kb + tig]);
                af[mt][2] = cvt_tf32(Es_[m*20     + kb + tig + 4]);
                af[mt][3] = cvt_tf32(Es_[(m+8)*20 + kb + tig + 4]);
            }
            #pragma unroll
            for (int nt = 0; nt < 4; nt++) {
                int n = wn*32 + nt*8 + gid;
                unsigned b0 = cvt_tf32(Vs_[(kb+tig)*72   + n]);
                unsigned b1 = cvt_tf32(Vs_[(kb+tig+4)*72 + n]);
                #pragma unroll
                for (int mt = 0; mt < 2; mt++)
                    mma_tf32(acc[mt][nt], af[mt][0],af[mt][1],af[mt][2],af[mt][3], b0, b1);
            }
        }
    }

    #pragma unroll
    for (int mt = 0; mt < 2; mt++) {
        int rl = wm*32 + mt*16 + gid;
        float z0 = zin[rl], z1 = zin[rl+8];
        #pragma unroll
        for (int nt = 0; nt < 4; nt++) {
            int cl = wn*32 + nt*8 + tig*2;
            float4 a = acc[mt][nt];
            size_t base = ((size_t)b*NT + bi0 + rl)*DM + h*HD + cl;
            *(float2*)(g_ctx + base)        = make_float2(a.x*z0, a.y*z0);
            *(float2*)(g_ctx + base + 8*DM) = make_float2(a.z*z1, a.w*z1);
        }
    }
}

// ---------------------------------------------------------------------------
__global__ __launch_bounds__(256)
void build_P_rownorm()
{
    const int rowi = blockIdx.x;
    const int b = rowi >> 11, i = rowi & 2047;
    const int tid = threadIdx.x;
    __shared__ float red[256];

    float v[8] = {0,0,0,0,0,0,0,0};
    #pragma unroll
    for (int h = 0; h < H; h++) {
        const float* ep = g_E + ((size_t)(b*H + h)*NT + i)*NT;
        float zi = g_Zi[(size_t)(b*H + h)*NT + i];
        #pragma unroll
        for (int k = 0; k < 8; k++)
            v[k] += ep[tid + k*256] * zi;
    }
    float s = 0.f;
    #pragma unroll
    for (int k = 0; k < 8; k++) {
        v[k] = expf(logf(v[k] * (1.0f/16.0f) + EPSF) * 10.0f);
        s += v[k];
    }
    red[tid] = s; __syncthreads();
    for (int o = 128; o > 0; o >>= 1) { if (tid < o) red[tid] += red[tid+o]; __syncthreads(); }
    float inv = 1.0f / (red[0] + EPSF);
    float* rp = g_P + (size_t)rowi * NT;
    #pragma unroll
    for (int k = 0; k < 8; k++) rp[tid + k*256] = v[k] * inv;
}

__global__ __launch_bounds__(256)
void colsum_part()
{
    const int j  = blockIdx.x * 256 + threadIdx.x;
    const int ch = blockIdx.y;
    const int b  = blockIdx.z;
    const float* p = g_P + (size_t)b*NT*NT + (size_t)ch*128*NT + j;
    float s = 0.f;
    #pragma unroll 8
    for (int i = 0; i < 128; i++) s += p[(size_t)i*NT];
    g_colpart[(ch*B + b)*NT + j] = s;
}

__global__ __launch_bounds__(256)
void colsum_combine()
{
    const int idx = blockIdx.x * 256 + threadIdx.x;
    const int b = idx >> 11, j = idx & 2047;
    float s = 0.f;
    #pragma unroll
    for (int ch = 0; ch < 16; ch++) s += g_colpart[(ch*B + b)*NT + j];
    g_colsum[idx] = s;
}

__global__ __launch_bounds__(256)
void coldiv_rownorm_kernel()
{
    const size_t rowi = blockIdx.x;
    const int b = (int)(rowi >> 11);
    float* rp = g_P + rowi * NT;
    const int tid = threadIdx.x;
    __shared__ float red[256];
    float v[8]; float s = 0.f;
    #pragma unroll
    for (int k = 0; k < 8; k++) {
        int j = tid + k*256;
        v[k] = rp[j] / (g_colsum[b*NT + j] + EPSF);
        s += v[k];
    }
    red[tid] = s; __syncthreads();
    for (int o = 128; o > 0; o >>= 1) { if (tid < o) red[tid] += red[tid+o]; __syncthreads(); }
    float inv = 1.0f / (red[0] + EPSF);
    #pragma unroll
    for (int k = 0; k < 8; k++) rp[tid + k*256] = v[k] * inv;
}

__global__ __launch_bounds__(256)
void cert_kernel(const float* __restrict__ cert, const float* __restrict__ ctemp,
                 float* __restrict__ out)
{
    const int idx = blockIdx.x * 256 + threadIdx.x;
    const int b = idx >> 11, i = idx & 2047;
    float s = 0.f;
    #pragma unroll
    for (int h = 0; h < H; h++) {
        size_t o = (size_t)(b*H + h)*NT + i;
        float Z = g_Z[o];
        s += logf(Z) - g_T[o] / Z;
    }
    float ent = s * (1.0f / 16.0f);
    float z = ctemp[0] * (logf(2048.0f) - ent);
    out[idx] = fmaxf(cert[idx], 1.0f / (1.0f + expf(-z)));
}

__global__ __launch_bounds__(256)
void argmax_gather_kernel(const int* __restrict__ perm, float* __restrict__ out)
{
    const int rowi = blockIdx.x;
    const int b = rowi >> 11;
    const float* rp = g_P + (size_t)rowi * NT;
    const int tid = threadIdx.x;
    __shared__ float bv[256];
    __shared__ int   bi[256];

    float best = -INFINITY; int bj = NT;
    #pragma unroll
    for (int s = 0; s < 8; s++) {
        int j = tid + s*256;
        float v = rp[j] / (g_colsum[b*NT + j] + EPSF);
        if (v > best) { best = v; bj = j; }
    }
    bv[tid] = best; bi[tid] = bj; __syncthreads();
    for (int o = 128; o > 0; o >>= 1) {
        if (tid < o) {
            if (bv[tid+o] > bv[tid] || (bv[tid+o] == bv[tid] && bi[tid+o] < bi[tid])) {
                bv[tid] = bv[tid+o]; bi[tid] = bi[tid+o];
            }
        }
        __syncthreads();
    }
    if (tid == 0) out[rowi] = (float)perm[(size_t)b*NT + bi[0]];
}

extern "C" void kernel_launch(void* const* d_in, const int* in_sizes, int n_in,
                              void* d_out, int out_size)
{
    const float* x     = (const float*)d_in[0];
    const float* cert  = (const float*)d_in[1];
    const int*   perm  = (const int*)  d_in[2];
    const float* Wq    = (const float*)d_in[3];
    const float* bq    = (const float*)d_in[4];
    const float* Wk    = (const float*)d_in[5];
    const float* bk    = (const float*)d_in[6];
    const float* Wv    = (const float*)d_in[7];
    const float* bvv   = (const float*)d_in[8];
    const float* Wo    = (const float*)d_in[9];
    const float* bo    = (const float*)d_in[10];
    const float* pbs   = (const float*)d_in[11];
    const float* ctemp = (const float*)d_in[12];
    float* out = (float*)d_out;

    float *pQ, *pK, *pV, *pCtx;
    cudaGetSymbolAddress((void**)&pQ,   g_Q);
    cudaGetSymbolAddress((void**)&pK,   g_K);
    cudaGetSymbolAddress((void**)&pV,   g_V);
    cudaGetSymbolAddress((void**)&pCtx, g_ctx);

    const int SMEM_G = 3*128*20*2*4;   // 61440
    const int SMEM_S = 16640*4;        // 66560
    cudaFuncSetAttribute(gemm_nt_mma,   cudaFuncAttributeMaxDynamicSharedMemorySize, SMEM_G);
    cudaFuncSetAttribute(scores_exp_mma,cudaFuncAttributeMaxDynamicSharedMemorySize, SMEM_S);

    const int M = B * NT;                  // 4096

    dim3 gProj(DM/128, M/128);             // (8, 32)
    gemm_nt_mma<<<gProj, 256, SMEM_G>>>(x, Wq, bq, pQ, DM, DM, 1);
    gemm_nt_mma<<<gProj, 256, SMEM_G>>>(x, Wk, bk, pK, DM, DM, 1);
    gemm_nt_mma<<<gProj, 256, SMEM_G>>>(x, Wv, bvv, pV, DM, DM, 1);

    dim3 gS(NT/128, B*H);                  // (16, 32)
    scores_exp_mma<<<gS, 256, SMEM_S>>>(pbs, perm);

    av_mma<<<gS, 256>>>();

    gemm_nt_mma<<<gProj, 256, SMEM_G>>>(pCtx, Wo, bo, out, DM, DM, 0);

    cert_kernel<<<(B*NT)/256, 256>>>(cert, ctemp, out + (size_t)M*DM);

    build_P_rownorm<<<B*NT, 256>>>();
    for (int it = 0; it < 10; it++) {
        colsum_part<<<dim3(NT/256, 16, B), 256>>>();
        colsum_combine<<<(B*NT)/256, 256>>>();
        if (it < 9) coldiv_rownorm_kernel<<<B*NT, 256>>>();
    }
    argmax_gather_kernel<<<B*NT, 256>>>(perm, out + (size_t)M*DM + B*NT);
}

// round 8
// speedup vs baseline: 1.3607x; 1.1372x over previous
#include <cuda_runtime.h>
#include <math.h>

#define B   2
#define NT  2048
#define DM  1024
#define H   16
#define HD  64
#define EPSF 1e-10f
#define NB_SINK 256

__device__ float g_Q[(size_t)B*H*NT*HD];
__device__ float g_K[(size_t)B*H*NT*HD];
__device__ float g_V[(size_t)B*H*NT*HD];
__device__ float g_E[(size_t)B*H*NT*NT];     // exp(scores), unnormalized
__device__ float g_P[(size_t)B*NT*NT];       // (mean_h attn + eps)^10, immutable
__device__ float g_ctx[(size_t)B*NT*DM];
__device__ float g_Z[(size_t)B*H*NT];
__device__ float g_T[(size_t)B*H*NT];
__device__ float g_Zi[(size_t)B*H*NT];
__device__ float g_u[B*NT];
__device__ float g_v[B*NT];
__device__ unsigned g_barcount = 0;
__device__ unsigned g_bargen = 0;

__device__ __forceinline__ unsigned cvt_tf32(float x){
    unsigned r; asm("cvt.rna.tf32.f32 %0, %1;" : "=r"(r) : "f"(x)); return r;
}
__device__ __forceinline__ void mma_tf32(float4 &c,
    unsigned a0, unsigned a1, unsigned a2, unsigned a3,
    unsigned b0, unsigned b1)
{
    asm("mma.sync.aligned.m16n8k8.row.col.f32.tf32.tf32.f32 "
        "{%0,%1,%2,%3},{%4,%5,%6,%7},{%8,%9},{%0,%1,%2,%3};"
        : "+f"(c.x), "+f"(c.y), "+f"(c.z), "+f"(c.w)
        : "r"(a0), "r"(a1), "r"(a2), "r"(a3), "r"(b0), "r"(b1));
}
__device__ __forceinline__ void cp16(unsigned d, const void* s){
    asm volatile("cp.async.cg.shared.global [%0], [%1], 16;\n" :: "r"(d), "l"(s));
}
__device__ __forceinline__ void cp_commit(){ asm volatile("cp.async.commit_group;\n"); }
__device__ __forceinline__ void cp_wait1(){ asm volatile("cp.async.wait_group 1;\n" ::: "memory"); }
__device__ __forceinline__ void cp_wait0(){ asm volatile("cp.async.wait_group 0;\n" ::: "memory"); }

// ---------------------------------------------------------------------------
// C[m][e] = sum_k A[m][k]*W[e][k] + bias[e].  128x128 tile, BK=16, tf32 mma,
// 3-stage cp.async pipeline.
// ---------------------------------------------------------------------------
__global__ __launch_bounds__(256, 2)
void gemm_nt_mma(const float* __restrict__ A, const float* __restrict__ W,
                 const float* __restrict__ bias, float* __restrict__ C,
                 int N, int K, int head_layout)
{
    extern __shared__ float smg[];
    float* Asm = smg;                // [3][128][20]
    float* Bsm = smg + 3*128*20;
    const unsigned sA = (unsigned)__cvta_generic_to_shared(Asm);
    const unsigned sB = (unsigned)__cvta_generic_to_shared(Bsm);

    const int tid = threadIdx.x, lane = tid & 31, warp = tid >> 5;
    const int gid = lane >> 2, tig = lane & 3;
    const int wm = warp & 1, wn = warp >> 1;
    const int bm0 = blockIdx.y * 128, bn0 = blockIdx.x * 128;
    const int lr = tid >> 1, lkq = (tid & 1) * 8;
    const float* Ag = A + (size_t)(bm0 + lr) * K + lkq;
    const float* Wg = W + (size_t)(bn0 + lr) * K + lkq;
    const int NCH = K / 16;

    float4 acc[4][4];
    #pragma unroll
    for (int i = 0; i < 4; i++)
        #pragma unroll
        for (int j = 0; j < 4; j++) acc[i][j] = make_float4(0.f,0.f,0.f,0.f);

    auto issue = [&](int cc){
        int st = cc % 3, k0 = cc * 16;
        unsigned da = sA + (unsigned)(((st*128 + lr)*20 + lkq)*4);
        cp16(da,      Ag + k0);
        cp16(da + 16, Ag + k0 + 4);
        unsigned db = sB + (unsigned)(((st*128 + lr)*20 + lkq)*4);
        cp16(db,      Wg + k0);
        cp16(db + 16, Wg + k0 + 4);
        cp_commit();
    };

    issue(0); issue(1);

    for (int c = 0; c < NCH; c++) {
        if (c + 1 < NCH) cp_wait1(); else cp_wait0();
        __syncthreads();
        if (c + 2 < NCH) issue(c + 2);
        const float* As_ = Asm + (c % 3)*128*20;
        const float* Bs_ = Bsm + (c % 3)*128*20;
        #pragma unroll
        for (int ks = 0; ks < 2; ks++) {
            const int kb = ks * 8;
            unsigned af[4][4];
            #pragma unroll
            for (int mt = 0; mt < 4; mt++) {
                int m = wm*64 + mt*16 + gid;
                af[mt][0] = cvt_tf32(As_[m*20     + kb + tig]);
                af[mt][1] = cvt_tf32(As_[(m+8)*20 + kb + tig]);
                af[mt][2] = cvt_tf32(As_[m*20     + kb + tig + 4]);
                af[mt][3] = cvt_tf32(As_[(m+8)*20 + kb + tig + 4]);
            }
            #pragma unroll
            for (int nt = 0; nt < 4; nt++) {
                int n = wn*32 + nt*8 + gid;
                unsigned b0 = cvt_tf32(Bs_[n*20 + kb + tig]);
                unsigned b1 = cvt_tf32(Bs_[n*20 + kb + tig + 4]);
                #pragma unroll
                for (int mt = 0; mt < 4; mt++)
                    mma_tf32(acc[mt][nt], af[mt][0],af[mt][1],af[mt][2],af[mt][3], b0, b1);
            }
        }
    }

    #pragma unroll
    for (int mt = 0; mt < 4; mt++) {
        int r0 = bm0 + wm*64 + mt*16 + gid;
        #pragma unroll
        for (int nt = 0; nt < 4; nt++) {
            int c0 = bn0 + wn*32 + nt*8 + tig*2;
            float bx = bias[c0], by = bias[c0+1];
            float2 lo = make_float2(acc[mt][nt].x + bx, acc[mt][nt].y + by);
            float2 hi = make_float2(acc[mt][nt].z + bx, acc[mt][nt].w + by);
            if (head_layout) {
                int bb = r0 >> 11, tok = r0 & 2047, hh = c0 >> 6, hd = c0 & 63;
                float* p = C + (((size_t)(bb*H + hh)*NT + tok)*HD) + hd;
                *(float2*)p = lo;
                *(float2*)(p + 8*HD) = hi;
            } else {
                float* p = C + (size_t)r0*N + c0;
                *(float2*)p = lo;
                *(float2*)(p + 8*(size_t)N) = hi;
            }
        }
    }
}

// ---------------------------------------------------------------------------
// Fused scores + exp + row Z/T/Zi.  Q pre-converted to tf32 at staging.
// dynamic smem: Qs[128][68] u32 | Ks[3][128][20] f32 | pfi,pfj = 66560 B
// ---------------------------------------------------------------------------
__global__ __launch_bounds__(256, 2)
void scores_exp_mma(const float* __restrict__ pbs, const int* __restrict__ perm)
{
    extern __shared__ float sms[];
    unsigned* Qs = (unsigned*)sms;       // [128][68] tf32 bits
    float* Ksm = sms + 8704;             // [3][128][20] raw fp32
    float* pfi = sms + 8704 + 7680;
    float* pfj = pfi + 128;
    const unsigned sK = (unsigned)__cvta_generic_to_shared(Ksm);

    const int tid = threadIdx.x, lane = tid & 31, warp = tid >> 5;
    const int gid = lane >> 2, tig = lane & 3;
    const int wm = warp & 1, wn = warp >> 1;
    const int bh = blockIdx.y, b = bh >> 4, h = bh & 15;
    const int bi0 = blockIdx.x * 128;
    const float pb = fabsf(pbs[h]);

    const float* Qg = g_Q + ((size_t)bh*NT + bi0)*HD;
    const float* Kbase = g_K + (size_t)bh*NT*HD;
    const int lr = tid >> 1, lkq = (tid & 1) * 8;

    // stage Q converted to tf32
    #pragma unroll
    for (int cq = 0; cq < 4; cq++) {
        int kk = lkq + cq*16;
        float4 q0 = *(const float4*)(Qg + (size_t)lr*HD + kk);
        float4 q1 = *(const float4*)(Qg + (size_t)lr*HD + kk + 4);
        uint4 t0, t1;
        t0.x=cvt_tf32(q0.x); t0.y=cvt_tf32(q0.y); t0.z=cvt_tf32(q0.z); t0.w=cvt_tf32(q0.w);
        t1.x=cvt_tf32(q1.x); t1.y=cvt_tf32(q1.y); t1.z=cvt_tf32(q1.z); t1.w=cvt_tf32(q1.w);
        *(uint4*)&Qs[lr*68 + kk]     = t0;
        *(uint4*)&Qs[lr*68 + kk + 4] = t1;
    }
    if (tid < 128) pfi[tid] = (float)perm[b*NT + bi0 + tid];

    float Zr[8] = {0,0,0,0,0,0,0,0};
    float Tr[8] = {0,0,0,0,0,0,0,0};

    auto issue = [&](int cc){
        int st = cc % 3, jt = cc >> 2, kc = (cc & 3) * 16;
        unsigned d = sK + (unsigned)(((st*128 + lr)*20 + lkq)*4);
        const float* s = Kbase + (size_t)(jt*128 + lr)*HD + kc + lkq;
        cp16(d, s); cp16(d + 16, s + 4);
        cp_commit();
    };

    issue(0); issue(1);
    const int NCH = 64;

    for (int jt = 0; jt < 16; jt++) {
        const int j0 = jt * 128;
        float4 acc[4][4];
        #pragma unroll
        for (int i = 0; i < 4; i++)
            #pragma unroll
            for (int j = 0; j < 4; j++) acc[i][j] = make_float4(0.f,0.f,0.f,0.f);

        #pragma unroll
        for (int k4 = 0; k4 < 4; k4++) {
            const int c = jt*4 + k4;
            if (c + 1 < NCH) cp_wait1(); else cp_wait0();
            __syncthreads();
            if (c + 2 < NCH) issue(c + 2);
            if (k4 == 0 && tid < 128) pfj[tid] = (float)perm[b*NT + j0 + tid];
            const float* Ks_ = Ksm + (c % 3)*128*20;
            const int kc = k4 * 16;
            #pragma unroll
            for (int ks = 0; ks < 2; ks++) {
                const int kb = ks * 8;
                unsigned af[4][4];
                #pragma unroll
                for (int mt = 0; mt < 4; mt++) {
                    int m = wm*64 + mt*16 + gid;
                    af[mt][0] = Qs[m*68     + kc + kb + tig];
                    af[mt][1] = Qs[(m+8)*68 + kc + kb + tig];
                    af[mt][2] = Qs[m*68     + kc + kb + tig + 4];
                    af[mt][3] = Qs[(m+8)*68 + kc + kb + tig + 4];
                }
                #pragma unroll
                for (int nt = 0; nt < 4; nt++) {
                    int n = wn*32 + nt*8 + gid;
                    unsigned b0 = cvt_tf32(Ks_[n*20 + kb + tig]);
                    unsigned b1 = cvt_tf32(Ks_[n*20 + kb + tig + 4]);
                    #pragma unroll
                    for (int mt = 0; mt < 4; mt++)
                        mma_tf32(acc[mt][nt], af[mt][0],af[mt][1],af[mt][2],af[mt][3], b0, b1);
                }
            }
        }

        #pragma unroll
        for (int mt = 0; mt < 4; mt++) {
            int rl = wm*64 + mt*16 + gid;
            float pa = pfi[rl], pc = pfi[rl+8];
            #pragma unroll
            for (int nt = 0; nt < 4; nt++) {
                int cl = wn*32 + nt*8 + tig*2;
                float d0 = pfj[cl], d1 = pfj[cl+1];
                float4 a = acc[mt][nt];
                float s00 = a.x*0.125f - fabsf(pa - d0)*pb;
                float s01 = a.y*0.125f - fabsf(pa - d1)*pb;
                float s10 = a.z*0.125f - fabsf(pc - d0)*pb;
                float s11 = a.w*0.125f - fabsf(pc - d1)*pb;
                float e00 = __expf(s00), e01 = __expf(s01);
                float e10 = __expf(s10), e11 = __expf(s11);
                Zr[mt*2]   += e00 + e01;  Tr[mt*2]   += s00*e00 + s01*e01;
                Zr[mt*2+1] += e10 + e11;  Tr[mt*2+1] += s10*e10 + s11*e11;
                size_t base = ((size_t)bh*NT + bi0 + rl)*NT + j0 + cl;
                *(float2*)(g_E + base)        = make_float2(e00, e01);
                *(float2*)(g_E + base + 8*NT) = make_float2(e10, e11);
            }
        }
    }

    float* red = (float*)Qs;
    const int pcol = wn*4 + tig;
    __syncthreads();
    #pragma unroll
    for (int mt = 0; mt < 4; mt++) {
        int r0 = wm*64 + mt*16 + gid;
        red[pcol*128 + r0]     = Zr[mt*2];
        red[pcol*128 + r0 + 8] = Zr[mt*2+1];
    }
    __syncthreads();
    if (tid < 128) {
        float s = 0.f;
        #pragma unroll
        for (int t = 0; t < 16; t++) s += red[t*128 + tid];
        g_Z[(size_t)bh*NT + bi0 + tid]  = s;
        g_Zi[(size_t)bh*NT + bi0 + tid] = 1.0f / s;
    }
    __syncthreads();
    #pragma unroll
    for (int mt = 0; mt < 4; mt++) {
        int r0 = wm*64 + mt*16 + gid;
        red[pcol*128 + r0]     = Tr[mt*2];
        red[pcol*128 + r0 + 8] = Tr[mt*2+1];
    }
    __syncthreads();
    if (tid < 128) {
        float s = 0.f;
        #pragma unroll
        for (int t = 0; t < 16; t++) s += red[t*128 + tid];
        g_T[(size_t)bh*NT + bi0 + tid] = s;
    }
}

// ---------------------------------------------------------------------------
// ctx = (E @ V) / Z.  3-stage cp.async; static smem.
// ---------------------------------------------------------------------------
__global__ __launch_bounds__(256, 2)
void av_mma()
{
    __shared__ float Es[3][128][20];
    __shared__ float Vs[3][16][72];
    __shared__ float zin[128];
    const unsigned sE = (unsigned)__cvta_generic_to_shared(&Es[0][0][0]);
    const unsigned sV = (unsigned)__cvta_generic_to_shared(&Vs[0][0][0]);

    const int tid = threadIdx.x, lane = tid & 31, warp = tid >> 5;
    const int gid = lane >> 2, tig = lane & 3;
    const int wm = warp >> 1, wn = warp & 1;
    const int bh = blockIdx.y, b = bh >> 4, h = bh & 15;
    const int bi0 = blockIdx.x * 128;

    const int lr = tid >> 1, lkq = (tid & 1) * 8;
    const float* Eg = g_E + ((size_t)bh*NT + bi0 + lr)*NT + lkq;
    const float* Vg = g_V + (size_t)bh*NT*HD;
    const int vr = tid >> 4, vcq = (tid & 15) * 4;

    if (tid < 128) zin[tid] = g_Zi[(size_t)bh*NT + bi0 + tid];

    float4 acc[2][4];
    #pragma unroll
    for (int i = 0; i < 2; i++)
        #pragma unroll
        for (int j = 0; j < 4; j++) acc[i][j] = make_float4(0.f,0.f,0.f,0.f);

    auto issue = [&](int cc){
        int st = cc % 3, k0 = cc * 16;
        unsigned dE = sE + (unsigned)(((st*128 + lr)*20 + lkq)*4);
        cp16(dE,      Eg + k0);
        cp16(dE + 16, Eg + k0 + 4);
        unsigned dV = sV + (unsigned)(((st*16 + vr)*72 + vcq)*4);
        cp16(dV, Vg + (size_t)(k0 + vr)*HD + vcq);
        cp_commit();
    };

    issue(0); issue(1);
    const int NCH = NT / 16;   // 128

    for (int c = 0; c < NCH; c++) {
        if (c + 1 < NCH) cp_wait1(); else cp_wait0();
        __syncthreads();
        if (c + 2 < NCH) issue(c + 2);
        const float* Es_ = &Es[c % 3][0][0];
        const float* Vs_ = &Vs[c % 3][0][0];
        #pragma unroll
        for (int ks = 0; ks < 2; ks++) {
            const int kb = ks * 8;
            unsigned af[2][4];
            #pragma unroll
            for (int mt = 0; mt < 2; mt++) {
                int m = wm*32 + mt*16 + gid;
                af[mt][0] = cvt_tf32(Es_[m*20     + kb + tig]);
                af[mt][1] = cvt_tf32(Es_[(m+8)*20 + kb + tig]);
                af[mt][2] = cvt_tf32(Es_[m*20     + kb + tig + 4]);
                af[mt][3] = cvt_tf32(Es_[(m+8)*20 + kb + tig + 4]);
            }
            #pragma unroll
            for (int nt = 0; nt < 4; nt++) {
                int n = wn*32 + nt*8 + gid;
                unsigned b0 = cvt_tf32(Vs_[(kb+tig)*72   + n]);
                unsigned b1 = cvt_tf32(Vs_[(kb+tig+4)*72 + n]);
                #pragma unroll
                for (int mt = 0; mt < 2; mt++)
                    mma_tf32(acc[mt][nt], af[mt][0],af[mt][1],af[mt][2],af[mt][3], b0, b1);
            }
        }
    }

    #pragma unroll
    for (int mt = 0; mt < 2; mt++) {
        int rl = wm*32 + mt*16 + gid;
        float z0 = zin[rl], z1 = zin[rl+8];
        #pragma unroll
        for (int nt = 0; nt < 4; nt++) {
            int cl = wn*32 + nt*8 + tig*2;
            float4 a = acc[mt][nt];
            size_t base = ((size_t)b*NT + bi0 + rl)*DM + h*HD + cl;
            *(float2*)(g_ctx + base)        = make_float2(a.x*z0, a.y*z0);
            *(float2*)(g_ctx + base + 8*DM) = make_float2(a.z*z1, a.w*z1);
        }
    }
}

// ---------------------------------------------------------------------------
// P raw: (mean_h attention + EPS)^10, elementwise (no normalization).
// ---------------------------------------------------------------------------
__global__ __launch_bounds__(256)
void build_P_kernel()
{
    size_t idx = (size_t)blockIdx.x * 256 + threadIdx.x;
    size_t b = idx / ((size_t)NT*NT);
    size_t rem = idx - b * (size_t)NT*NT;
    int i = (int)(rem >> 11);
    float s = 0.f;
    #pragma unroll
    for (int h = 0; h < H; h++)
        s += g_E[(size_t)(b*H + h)*NT*NT + rem] * g_Zi[(size_t)(b*H + h)*NT + i];
    float avg = s * (1.0f / 16.0f);
    g_P[idx] = expf(logf(avg + EPSF) * 10.0f);
}

// ---------------------------------------------------------------------------
// Persistent Sinkhorn (diagonal scaling) + argmax + gather.  One launch.
// 256 blocks x 256 threads, guaranteed co-resident (2/SM on 148 SMs).
// ---------------------------------------------------------------------------
__device__ __forceinline__ void grid_sync(unsigned &gen)
{
    __syncthreads();
    if (threadIdx.x == 0) {
        gen++;
        __threadfence();
        unsigned old = atomicAdd(&g_barcount, 1);
        if (old == NB_SINK - 1) {
            atomicExch(&g_barcount, 0);
            atomicExch(&g_bargen, gen);
        } else {
            while (*(volatile unsigned*)&g_bargen < gen) __nanosleep(64);
        }
    }
    __syncthreads();
}

__global__ __launch_bounds__(256)
void sinkhorn_persist(const int* __restrict__ perm, float* __restrict__ outp)
{
    __shared__ float sv[NT];
    __shared__ float red[256];
    const int tid = threadIdx.x;
    const int bk = blockIdx.x;
    const int lane = tid & 31, w = tid >> 5;
    unsigned gen = *(volatile unsigned*)&g_bargen;

    const int row0 = bk * 16;            // 16 rows per block (global row = b*2048+i)
    const int bb = row0 >> 11;           // batch of this block's rows/cols
    const int jbase = row0 & 2047;       // 16 columns per block

    if (tid < 16) { __stcg(&g_u[row0 + tid], 1.0f); __stcg(&g_v[row0 + tid], 1.0f); }
    grid_sync(gen);

    for (int it = 0; it < 10; it++) {
        // phase R: u_i = u_i / (u_i*(P v)_i + eps)
        for (int j = tid; j < NT; j += 256) sv[j] = __ldcg(&g_v[bb*NT + j]);
        __syncthreads();
        #pragma unroll
        for (int rr = 0; rr < 2; rr++) {
            int r = row0 + w*2 + rr;
            const float* Pr = g_P + (size_t)r * NT;
            float s = 0.f;
            #pragma unroll 8
            for (int j = lane; j < NT; j += 32) s += Pr[j] * sv[j];
            #pragma unroll
            for (int o = 16; o > 0; o >>= 1) s += __shfl_xor_sync(0xffffffffu, s, o);
            if (lane == 0) {
                float u = __ldcg(&g_u[r]);
                __stcg(&g_u[r], u / (u * s + EPSF));
            }
        }
        grid_sync(gen);

        // phase C: v_j = v_j / (v_j*(P^T u)_j + eps)
        for (int i = tid; i < NT; i += 256) sv[i] = __ldcg(&g_u[bb*NT + i]);
        __syncthreads();
        {
            int c = tid & 15, rg = tid >> 4;     // 16 cols x 16 row-groups
            const float* Pc = g_P + (size_t)bb*NT*NT + jbase + c;
            float s = 0.f;
            #pragma unroll 8
            for (int i = rg; i < NT; i += 16) s += Pc[(size_t)i*NT] * sv[i];
            red[tid] = s; __syncthreads();
            if (tid < 128) red[tid] += red[tid+128];
            __syncthreads();
            if (tid < 64)  red[tid] += red[tid+64];
            __syncthreads();
            if (tid < 32)  red[tid] += red[tid+32];
            __syncthreads();
            if (tid < 16) {
                float tot = red[tid] + red[tid+16];
                int jj = bb*NT + jbase + tid;
                float v = __ldcg(&g_v[jj]);
                __stcg(&g_v[jj], v / (v * tot + EPSF));
            }
            __syncthreads();
        }
        grid_sync(gen);
    }

    // argmax_j of P_ij * v_j (u_i > 0 constant per row), first max wins
    for (int j = tid; j < NT; j += 256) sv[j] = __ldcg(&g_v[bb*NT + j]);
    __syncthreads();
    #pragma unroll
    for (int rr = 0; rr < 2; rr++) {
        int r = row0 + w*2 + rr;
        const float* Pr = g_P + (size_t)r * NT;
        float best = -INFINITY; int bj = NT;
        for (int j = lane; j < NT; j += 32) {
            float val = Pr[j] * sv[j];
            if (val > best) { best = val; bj = j; }
        }
        #pragma unroll
        for (int o = 16; o > 0; o >>= 1) {
            float ob = __shfl_xor_sync(0xffffffffu, best, o);
            int   oj = __shfl_xor_sync(0xffffffffu, bj, o);
            if (ob > best || (ob == best && oj < bj)) { best = ob; bj = oj; }
        }
        if (lane == 0) outp[r] = (float)perm[bb*NT + bj];
    }
}

// ---------------------------------------------------------------------------
__global__ __launch_bounds__(256)
void cert_kernel(const float* __restrict__ cert, const float* __restrict__ ctemp,
                 float* __restrict__ out)
{
    const int idx = blockIdx.x * 256 + threadIdx.x;
    const int b = idx >> 11, i = idx & 2047;
    float s = 0.f;
    #pragma unroll
    for (int h = 0; h < H; h++) {
        size_t o = (size_t)(b*H + h)*NT + i;
        float Z = g_Z[o];
        s += logf(Z) - g_T[o] / Z;
    }
    float ent = s * (1.0f / 16.0f);
    float z = ctemp[0] * (logf(2048.0f) - ent);
    out[idx] = fmaxf(cert[idx], 1.0f / (1.0f + expf(-z)));
}

extern "C" void kernel_launch(void* const* d_in, const int* in_sizes, int n_in,
                              void* d_out, int out_size)
{
    const float* x     = (const float*)d_in[0];
    const float* cert  = (const float*)d_in[1];
    const int*   perm  = (const int*)  d_in[2];
    const float* Wq    = (const float*)d_in[3];
    const float* bq    = (const float*)d_in[4];
    const float* Wk    = (const float*)d_in[5];
    const float* bk    = (const float*)d_in[6];
    const float* Wv    = (const float*)d_in[7];
    const float* bvv   = (const float*)d_in[8];
    const float* Wo    = (const float*)d_in[9];
    const float* bo    = (const float*)d_in[10];
    const float* pbs   = (const float*)d_in[11];
    const float* ctemp = (const float*)d_in[12];
    float* out = (float*)d_out;

    float *pQ, *pK, *pV, *pCtx;
    cudaGetSymbolAddress((void**)&pQ,   g_Q);
    cudaGetSymbolAddress((void**)&pK,   g_K);
    cudaGetSymbolAddress((void**)&pV,   g_V);
    cudaGetSymbolAddress((void**)&pCtx, g_ctx);

    const int SMEM_G = 3*128*20*2*4;   // 61440
    const int SMEM_S = 16640*4;        // 66560
    cudaFuncSetAttribute(gemm_nt_mma,   cudaFuncAttributeMaxDynamicSharedMemorySize, SMEM_G);
    cudaFuncSetAttribute(scores_exp_mma,cudaFuncAttributeMaxDynamicSharedMemorySize, SMEM_S);

    const int M = B * NT;                  // 4096

    dim3 gProj(DM/128, M/128);             // (8, 32)
    gemm_nt_mma<<<gProj, 256, SMEM_G>>>(x, Wq, bq, pQ, DM, DM, 1);
    gemm_nt_mma<<<gProj, 256, SMEM_G>>>(x, Wk, bk, pK, DM, DM, 1);
    gemm_nt_mma<<<gProj, 256, SMEM_G>>>(x, Wv, bvv, pV, DM, DM, 1);

    dim3 gS(NT/128, B*H);                  // (16, 32)
    scores_exp_mma<<<gS, 256, SMEM_S>>>(pbs, perm);

    av_mma<<<gS, 256>>>();

    gemm_nt_mma<<<gProj, 256, SMEM_G>>>(pCtx, Wo, bo, out, DM, DM, 0);

    cert_kernel<<<(B*NT)/256, 256>>>(cert, ctemp, out + (size_t)M*DM);

    build_P_kernel<<<32768, 256>>>();
    sinkhorn_persist<<<NB_SINK, 256>>>(perm, out + (size_t)M*DM + B*NT);
}